// round 1
// baseline (speedup 1.0000x reference)
#include <cuda_runtime.h>

#define BSZ 32
#define CDIM 512
#define TDIM 1024
#define SCALE_F 0.04419417382415922f  // 1/sqrt(512)

// Scratch (allocation-free rule: __device__ globals)
__device__ float g_q[(size_t)BSZ * CDIM * TDIM];
__device__ float g_k[(size_t)BSZ * CDIM * TDIM];
__device__ float g_v[(size_t)BSZ * CDIM * TDIM];
__device__ float g_e[(size_t)BSZ * CDIM * CDIM];

// ---------------------------------------------------------------------------
// 128x128 tile SGEMM core, BK=8, 256 threads, 8x8 per-thread microtile.
// A is [M,K] row-major (K contiguous), pre-offset to block row (A += m0*lda).
// BT=false: B is [K,N] row-major (N contiguous), pre-offset to block col (B += n0).
// BT=true : B is [N,K] row-major (K contiguous), pre-offset to block row (B += n0*ldb).
// ---------------------------------------------------------------------------
template <bool BT>
__device__ __forceinline__ void gemm_tile_128(
    const float* __restrict__ A, int lda,
    const float* __restrict__ B, int ldb,
    int K, float acc[8][8])
{
    __shared__ float As[8][128];
    __shared__ float Bs[8][128];

    const int tid = threadIdx.x;
    const int tx = tid & 15;
    const int ty = tid >> 4;

#pragma unroll
    for (int i = 0; i < 8; i++)
#pragma unroll
        for (int j = 0; j < 8; j++) acc[i][j] = 0.0f;

    const int arow = tid >> 1;           // 0..127
    const int akc  = (tid & 1) * 4;      // 0 or 4
    const int bkk  = tid >> 5;           // 0..7   (BT=false path)
    const int bn   = (tid & 31) * 4;     // 0..124 (BT=false path)

    for (int kt = 0; kt < K; kt += 8) {
        // load A tile (transpose into As[k][m])
        float4 av = *reinterpret_cast<const float4*>(A + (size_t)arow * lda + kt + akc);
        As[akc + 0][arow] = av.x;
        As[akc + 1][arow] = av.y;
        As[akc + 2][arow] = av.z;
        As[akc + 3][arow] = av.w;

        if (!BT) {
            float4 bv = *reinterpret_cast<const float4*>(B + (size_t)(kt + bkk) * ldb + bn);
            *reinterpret_cast<float4*>(&Bs[bkk][bn]) = bv;
        } else {
            float4 bv = *reinterpret_cast<const float4*>(B + (size_t)arow * ldb + kt + akc);
            Bs[akc + 0][arow] = bv.x;
            Bs[akc + 1][arow] = bv.y;
            Bs[akc + 2][arow] = bv.z;
            Bs[akc + 3][arow] = bv.w;
        }
        __syncthreads();

#pragma unroll
        for (int kk = 0; kk < 8; kk++) {
            float a[8], b[8];
            *reinterpret_cast<float4*>(a)     = *reinterpret_cast<const float4*>(&As[kk][ty * 8]);
            *reinterpret_cast<float4*>(a + 4) = *reinterpret_cast<const float4*>(&As[kk][ty * 8 + 4]);
            *reinterpret_cast<float4*>(b)     = *reinterpret_cast<const float4*>(&Bs[kk][tx * 8]);
            *reinterpret_cast<float4*>(b + 4) = *reinterpret_cast<const float4*>(&Bs[kk][tx * 8 + 4]);
#pragma unroll
            for (int i = 0; i < 8; i++)
#pragma unroll
                for (int j = 0; j < 8; j++)
                    acc[i][j] = fmaf(a[i], b[j], acc[i][j]);
        }
        __syncthreads();
    }
}

// ---------------------------------------------------------------------------
// 1) Q/K/V projection: out_dt[b,d,t] = gate[b,d,t] * (sum_c W[d,c]*x[b,c,t] + bias[d])
//    grid: (T/128, C/128, 3*B), z = m*BSZ + b
// ---------------------------------------------------------------------------
__global__ __launch_bounds__(256) void qkv_kernel(
    const float* __restrict__ x,
    const float* __restrict__ gq, const float* __restrict__ gk, const float* __restrict__ gv,
    const float* __restrict__ Wq, const float* __restrict__ bq,
    const float* __restrict__ Wk, const float* __restrict__ bk,
    const float* __restrict__ Wv, const float* __restrict__ bv)
{
    const int z = blockIdx.z;
    const int b = z & 31;
    const int m = z >> 5;   // 0=q 1=k 2=v

    const float* W;  const float* bias; const float* gate; float* out;
    if (m == 0)      { W = Wq; bias = bq; gate = gq; out = g_q; }
    else if (m == 1) { W = Wk; bias = bk; gate = gk; out = g_k; }
    else             { W = Wv; bias = bv; gate = gv; out = g_v; }

    const int m0 = blockIdx.y * 128;  // d
    const int n0 = blockIdx.x * 128;  // t
    const size_t base = (size_t)b * CDIM * TDIM;

    float acc[8][8];
    gemm_tile_128<false>(W + (size_t)m0 * CDIM, CDIM,
                         x + base + n0, TDIM, CDIM, acc);

    const int tx = threadIdx.x & 15;
    const int ty = threadIdx.x >> 4;
#pragma unroll
    for (int i = 0; i < 8; i++) {
        const int d = m0 + ty * 8 + i;
        const float bi = bias[d];
        const size_t rowoff = base + (size_t)d * TDIM;
#pragma unroll
        for (int j = 0; j < 8; j++) {
            const int t = n0 + tx * 8 + j;
            out[rowoff + t] = (acc[i][j] + bi) * gate[rowoff + t];
        }
    }
}

// ---------------------------------------------------------------------------
// 2) energy: E[b,c,d] = SCALE * sum_t Q_dt[b,c,t] * K_dt[b,d,t]
//    grid: (C/128, C/128, B)
// ---------------------------------------------------------------------------
__global__ __launch_bounds__(256) void energy_kernel()
{
    const int b  = blockIdx.z;
    const int m0 = blockIdx.y * 128;  // c
    const int n0 = blockIdx.x * 128;  // d
    const size_t base = (size_t)b * CDIM * TDIM;

    float acc[8][8];
    gemm_tile_128<true>(g_q + base + (size_t)m0 * TDIM, TDIM,
                        g_k + base + (size_t)n0 * TDIM, TDIM, TDIM, acc);

    const int tx = threadIdx.x & 15;
    const int ty = threadIdx.x >> 4;
    const size_t ebase = (size_t)b * CDIM * CDIM;
#pragma unroll
    for (int i = 0; i < 8; i++) {
        const int c = m0 + ty * 8 + i;
#pragma unroll
        for (int j = 0; j < 8; j++) {
            const int d = n0 + tx * 8 + j;
            g_e[ebase + (size_t)c * CDIM + d] = acc[i][j] * SCALE_F;
        }
    }
}

// ---------------------------------------------------------------------------
// 3) row softmax over d (row length 512). One block (256 thr) per row, in-place.
// ---------------------------------------------------------------------------
__global__ __launch_bounds__(256) void softmax_kernel()
{
    const size_t row = blockIdx.x;
    float* e = g_e + row * CDIM;
    const int tid  = threadIdx.x;
    const int lane = tid & 31;
    const int warp = tid >> 5;

    __shared__ float wmax[8];
    __shared__ float wsum[8];

    float v0 = e[tid];
    float v1 = e[tid + 256];

    float m = fmaxf(v0, v1);
#pragma unroll
    for (int o = 16; o > 0; o >>= 1)
        m = fmaxf(m, __shfl_xor_sync(0xFFFFFFFFu, m, o));
    if (lane == 0) wmax[warp] = m;
    __syncthreads();
    float bm = wmax[0];
#pragma unroll
    for (int w = 1; w < 8; w++) bm = fmaxf(bm, wmax[w]);

    float e0 = __expf(v0 - bm);
    float e1 = __expf(v1 - bm);
    float s = e0 + e1;
#pragma unroll
    for (int o = 16; o > 0; o >>= 1)
        s += __shfl_xor_sync(0xFFFFFFFFu, s, o);
    if (lane == 0) wsum[warp] = s;
    __syncthreads();
    float bs = 0.0f;
#pragma unroll
    for (int w = 0; w < 8; w++) bs += wsum[w];

    const float inv = 1.0f / bs;
    e[tid]       = e0 * inv;
    e[tid + 256] = e1 * inv;
}

// ---------------------------------------------------------------------------
// 4) out[b,c,t] = sum_d attn[b,c,d] * V_dt[b,d,t]
//    grid: (T/128, C/128, B)
// ---------------------------------------------------------------------------
__global__ __launch_bounds__(256) void out_kernel(float* __restrict__ out)
{
    const int b  = blockIdx.z;
    const int m0 = blockIdx.y * 128;  // c
    const int n0 = blockIdx.x * 128;  // t
    const size_t base  = (size_t)b * CDIM * TDIM;
    const size_t ebase = (size_t)b * CDIM * CDIM;

    float acc[8][8];
    gemm_tile_128<false>(g_e + ebase + (size_t)m0 * CDIM, CDIM,
                         g_v + base + n0, TDIM, CDIM, acc);

    const int tx = threadIdx.x & 15;
    const int ty = threadIdx.x >> 4;
#pragma unroll
    for (int i = 0; i < 8; i++) {
        const int c = m0 + ty * 8 + i;
        const size_t rowoff = base + (size_t)c * TDIM;
#pragma unroll
        for (int j = 0; j < 8; j++) {
            out[rowoff + n0 + tx * 8 + j] = acc[i][j];
        }
    }
}

// ---------------------------------------------------------------------------
extern "C" void kernel_launch(void* const* d_in, const int* in_sizes, int n_in,
                              void* d_out, int out_size)
{
    const float* x  = (const float*)d_in[0];
    const float* gq = (const float*)d_in[1];
    const float* gk = (const float*)d_in[2];
    const float* gv = (const float*)d_in[3];
    const float* Wq = (const float*)d_in[4];
    const float* bq = (const float*)d_in[5];
    const float* Wk = (const float*)d_in[6];
    const float* bk = (const float*)d_in[7];
    const float* Wv = (const float*)d_in[8];
    const float* bv = (const float*)d_in[9];
    float* out = (float*)d_out;

    dim3 blk(256);

    dim3 g1(TDIM / 128, CDIM / 128, 3 * BSZ);
    qkv_kernel<<<g1, blk>>>(x, gq, gk, gv, Wq, bq, Wk, bk, Wv, bv);

    dim3 g2(CDIM / 128, CDIM / 128, BSZ);
    energy_kernel<<<g2, blk>>>();

    softmax_kernel<<<BSZ * CDIM, blk>>>();

    dim3 g4(TDIM / 128, CDIM / 128, BSZ);
    out_kernel<<<g4, blk>>>(out);
}

// round 2
// speedup vs baseline: 2.2914x; 2.2914x over previous
#include <cuda_runtime.h>
#include <cuda_bf16.h>
#include <cstdint>

#define BSZ 32
#define CDIM 512
#define TDIM 1024
#define SCALE_F 0.04419417382415922f  // 1/sqrt(512)

// Scratch (allocation-free rule: __device__ globals)
__device__ __align__(16) float g_q[(size_t)BSZ * CDIM * TDIM];
__device__ __align__(16) float g_k[(size_t)BSZ * CDIM * TDIM];
__device__ __align__(16) float g_v[(size_t)BSZ * CDIM * TDIM];
__device__ __align__(16) float g_e[(size_t)BSZ * CDIM * CDIM];

// SMEM strides (bf16 elements) chosen for conflict-free ldmatrix:
// A rows 80B apart -> distinct 16B chunks mod 128B; B rows 272B apart -> same.
#define ASTR 40
#define BSTR 136

// ---------------------------------------------------------------------------
// PTX wrappers
// ---------------------------------------------------------------------------
__device__ __forceinline__ void ldsm4(uint32_t& r0, uint32_t& r1, uint32_t& r2, uint32_t& r3,
                                      const void* p) {
    uint32_t a = (uint32_t)__cvta_generic_to_shared(p);
    asm volatile("ldmatrix.sync.aligned.m8n8.x4.shared.b16 {%0,%1,%2,%3},[%4];"
                 : "=r"(r0), "=r"(r1), "=r"(r2), "=r"(r3) : "r"(a));
}
__device__ __forceinline__ void ldsm4t(uint32_t& r0, uint32_t& r1, uint32_t& r2, uint32_t& r3,
                                       const void* p) {
    uint32_t a = (uint32_t)__cvta_generic_to_shared(p);
    asm volatile("ldmatrix.sync.aligned.m8n8.x4.trans.shared.b16 {%0,%1,%2,%3},[%4];"
                 : "=r"(r0), "=r"(r1), "=r"(r2), "=r"(r3) : "r"(a));
}
__device__ __forceinline__ void mma16816(float* d, const uint32_t* a, const uint32_t* b) {
    asm volatile(
        "mma.sync.aligned.m16n8k16.row.col.f32.bf16.bf16.f32 "
        "{%0,%1,%2,%3},{%4,%5,%6,%7},{%8,%9},{%0,%1,%2,%3};"
        : "+f"(d[0]), "+f"(d[1]), "+f"(d[2]), "+f"(d[3])
        : "r"(a[0]), "r"(a[1]), "r"(a[2]), "r"(a[3]), "r"(b[0]), "r"(b[1]));
}

__device__ __forceinline__ void split1(float f, __nv_bfloat16& h, __nv_bfloat16& l) {
    h = __float2bfloat16(f);
    l = __float2bfloat16(f - __bfloat162float(h));
}

// ---------------------------------------------------------------------------
// 128x128 block-tile GEMM on tensor cores, bf16 split-3 from fp32 operands.
// 256 threads = 8 warps arranged 4(M) x 2(N); warp tile 32x64.
// A: [M,K] row-major, pre-offset to block row.
// BT=false: B [K,N] row-major, pre-offset to block col.
// BT=true : B [N,K] row-major, pre-offset to block row.
// acc[mi][ni][4] per thread (mi: 2 m16 tiles, ni: 8 n8 tiles).
// ---------------------------------------------------------------------------
template <bool BT>
__device__ __forceinline__ void gemm_mma_tile(
    const float* __restrict__ A, int lda,
    const float* __restrict__ B, int ldb,
    int K, float acc[2][8][4])
{
    __shared__ __nv_bfloat16 Ah[128 * ASTR], Al[128 * ASTR];
    __shared__ __nv_bfloat16 Bh[32 * BSTR], Bl[32 * BSTR];

    const int tid  = threadIdx.x;
    const int lane = tid & 31;
    const int wid  = tid >> 5;
    const int wm   = wid & 3;   // 0..3 -> m offset wm*32
    const int wn   = wid >> 2;  // 0..1 -> n offset wn*64

#pragma unroll
    for (int mi = 0; mi < 2; mi++)
#pragma unroll
        for (int ni = 0; ni < 8; ni++)
#pragma unroll
            for (int r = 0; r < 4; r++) acc[mi][ni][r] = 0.0f;

    for (int kt = 0; kt < K; kt += 32) {
        // ---- stage A tile: 128 rows x 32 k (fp32 -> split bf16) ----
#pragma unroll
        for (int i = 0; i < 4; i++) {
            int row = i * 32 + (tid >> 3);
            int col = (tid & 7) * 4;
            float4 v = *reinterpret_cast<const float4*>(A + (size_t)row * lda + kt + col);
            __nv_bfloat16 h, l;
            __nv_bfloat16* ph = &Ah[row * ASTR + col];
            __nv_bfloat16* pl = &Al[row * ASTR + col];
            split1(v.x, h, l); ph[0] = h; pl[0] = l;
            split1(v.y, h, l); ph[1] = h; pl[1] = l;
            split1(v.z, h, l); ph[2] = h; pl[2] = l;
            split1(v.w, h, l); ph[3] = h; pl[3] = l;
        }
        // ---- stage B tile: 32 k x 128 n ----
        if (!BT) {
#pragma unroll
            for (int i = 0; i < 4; i++) {
                int row = i * 8 + (tid >> 5);     // k row
                int col = (tid & 31) * 4;         // n
                float4 v = *reinterpret_cast<const float4*>(B + (size_t)(kt + row) * ldb + col);
                __nv_bfloat16 h, l;
                __nv_bfloat16* ph = &Bh[row * BSTR + col];
                __nv_bfloat16* pl = &Bl[row * BSTR + col];
                split1(v.x, h, l); ph[0] = h; pl[0] = l;
                split1(v.y, h, l); ph[1] = h; pl[1] = l;
                split1(v.z, h, l); ph[2] = h; pl[2] = l;
                split1(v.w, h, l); ph[3] = h; pl[3] = l;
            }
        } else {
            // B global is [N,K] row-major; transpose into Bs[k][n]
#pragma unroll
            for (int i = 0; i < 4; i++) {
                int n = i * 32 + (tid >> 3);
                int c = (tid & 7) * 4;            // k offset within chunk
                float4 v = *reinterpret_cast<const float4*>(B + (size_t)n * ldb + kt + c);
                __nv_bfloat16 h, l;
                split1(v.x, h, l); Bh[(c + 0) * BSTR + n] = h; Bl[(c + 0) * BSTR + n] = l;
                split1(v.y, h, l); Bh[(c + 1) * BSTR + n] = h; Bl[(c + 1) * BSTR + n] = l;
                split1(v.z, h, l); Bh[(c + 2) * BSTR + n] = h; Bl[(c + 2) * BSTR + n] = l;
                split1(v.w, h, l); Bh[(c + 3) * BSTR + n] = h; Bl[(c + 3) * BSTR + n] = l;
            }
        }
        __syncthreads();

#pragma unroll
        for (int ks = 0; ks < 2; ks++) {
            // A fragments (hi/lo), 2 m16 tiles
            uint32_t ah[2][4], al_[2][4];
#pragma unroll
            for (int mi = 0; mi < 2; mi++) {
                int arow = wm * 32 + mi * 16 + (lane & 15);
                int acol = ks * 16 + (lane >> 4) * 8;
                ldsm4(ah[mi][0], ah[mi][1], ah[mi][2], ah[mi][3], &Ah[arow * ASTR + acol]);
                ldsm4(al_[mi][0], al_[mi][1], al_[mi][2], al_[mi][3], &Al[arow * ASTR + acol]);
            }
            // B fragments (hi/lo), 8 n8 tiles loaded as 4 n16 pairs
            uint32_t bh[4][4], bl_[4][4];
#pragma unroll
            for (int p = 0; p < 4; p++) {
                int brow = ks * 16 + (lane & 15);
                int bcol = wn * 64 + p * 16 + (lane >> 4) * 8;
                ldsm4t(bh[p][0], bh[p][1], bh[p][2], bh[p][3], &Bh[brow * BSTR + bcol]);
                ldsm4t(bl_[p][0], bl_[p][1], bl_[p][2], bl_[p][3], &Bl[brow * BSTR + bcol]);
            }
#pragma unroll
            for (int mi = 0; mi < 2; mi++) {
#pragma unroll
                for (int p = 0; p < 4; p++) {
#pragma unroll
                    for (int t = 0; t < 2; t++) {
                        const int ni = p * 2 + t;
                        const uint32_t* bhp = &bh[p][t * 2];
                        const uint32_t* blp = &bl_[p][t * 2];
                        mma16816(acc[mi][ni], ah[mi], bhp);   // hi*hi
                        mma16816(acc[mi][ni], ah[mi], blp);   // hi*lo
                        mma16816(acc[mi][ni], al_[mi], bhp);  // lo*hi
                    }
                }
            }
        }
        __syncthreads();
    }
}

// ---------------------------------------------------------------------------
// 1) Q/K/V projection: out_dt[b,d,t] = gate[b,d,t]*(sum_c W[d,c]*x[b,c,t] + b[d])
//    grid: (T/128, C/128, 3*B)
// ---------------------------------------------------------------------------
__global__ __launch_bounds__(256) void qkv_kernel(
    const float* __restrict__ x,
    const float* __restrict__ gq, const float* __restrict__ gk, const float* __restrict__ gv,
    const float* __restrict__ Wq, const float* __restrict__ bq,
    const float* __restrict__ Wk, const float* __restrict__ bk,
    const float* __restrict__ Wv, const float* __restrict__ bv)
{
    const int z = blockIdx.z;
    const int b = z & 31;
    const int m = z >> 5;

    const float* W; const float* bias; const float* gate; float* out;
    if (m == 0)      { W = Wq; bias = bq; gate = gq; out = g_q; }
    else if (m == 1) { W = Wk; bias = bk; gate = gk; out = g_k; }
    else             { W = Wv; bias = bv; gate = gv; out = g_v; }

    const int m0 = blockIdx.y * 128;
    const int n0 = blockIdx.x * 128;
    const size_t base = (size_t)b * CDIM * TDIM;

    float acc[2][8][4];
    gemm_mma_tile<false>(W + (size_t)m0 * CDIM, CDIM, x + base + n0, TDIM, CDIM, acc);

    const int lane = threadIdx.x & 31;
    const int wid  = threadIdx.x >> 5;
    const int wm = wid & 3, wn = wid >> 2;
#pragma unroll
    for (int mi = 0; mi < 2; mi++) {
#pragma unroll
        for (int ni = 0; ni < 8; ni++) {
            int r = m0 + wm * 32 + mi * 16 + (lane >> 2);
            int c = n0 + wn * 64 + ni * 8 + (lane & 3) * 2;
#pragma unroll
            for (int half = 0; half < 2; half++) {
                int d = r + half * 8;
                float bi = bias[d];
                size_t off = base + (size_t)d * TDIM + c;
                out[off]     = (acc[mi][ni][half * 2 + 0] + bi) * gate[off];
                out[off + 1] = (acc[mi][ni][half * 2 + 1] + bi) * gate[off + 1];
            }
        }
    }
}

// ---------------------------------------------------------------------------
// 2) energy: E[b,c,d] = SCALE * sum_t Q[b,c,t]*K[b,d,t]    grid (C/128,C/128,B)
// ---------------------------------------------------------------------------
__global__ __launch_bounds__(256) void energy_kernel()
{
    const int b  = blockIdx.z;
    const int m0 = blockIdx.y * 128;
    const int n0 = blockIdx.x * 128;
    const size_t base = (size_t)b * CDIM * TDIM;

    float acc[2][8][4];
    gemm_mma_tile<true>(g_q + base + (size_t)m0 * TDIM, TDIM,
                        g_k + base + (size_t)n0 * TDIM, TDIM, TDIM, acc);

    const int lane = threadIdx.x & 31;
    const int wid  = threadIdx.x >> 5;
    const int wm = wid & 3, wn = wid >> 2;
    const size_t ebase = (size_t)b * CDIM * CDIM;
#pragma unroll
    for (int mi = 0; mi < 2; mi++) {
#pragma unroll
        for (int ni = 0; ni < 8; ni++) {
            int r = m0 + wm * 32 + mi * 16 + (lane >> 2);
            int c = n0 + wn * 64 + ni * 8 + (lane & 3) * 2;
#pragma unroll
            for (int half = 0; half < 2; half++) {
                size_t off = ebase + (size_t)(r + half * 8) * CDIM + c;
                g_e[off]     = acc[mi][ni][half * 2 + 0] * SCALE_F;
                g_e[off + 1] = acc[mi][ni][half * 2 + 1] * SCALE_F;
            }
        }
    }
}

// ---------------------------------------------------------------------------
// 3) row softmax over d (512). One block (256 thr) per row, in-place.
// ---------------------------------------------------------------------------
__global__ __launch_bounds__(256) void softmax_kernel()
{
    const size_t row = blockIdx.x;
    float* e = g_e + row * CDIM;
    const int tid  = threadIdx.x;
    const int lane = tid & 31;
    const int warp = tid >> 5;

    __shared__ float wmax[8];
    __shared__ float wsum[8];

    float v0 = e[tid];
    float v1 = e[tid + 256];

    float m = fmaxf(v0, v1);
#pragma unroll
    for (int o = 16; o > 0; o >>= 1)
        m = fmaxf(m, __shfl_xor_sync(0xFFFFFFFFu, m, o));
    if (lane == 0) wmax[warp] = m;
    __syncthreads();
    float bm = wmax[0];
#pragma unroll
    for (int w = 1; w < 8; w++) bm = fmaxf(bm, wmax[w]);

    float e0 = __expf(v0 - bm);
    float e1 = __expf(v1 - bm);
    float s = e0 + e1;
#pragma unroll
    for (int o = 16; o > 0; o >>= 1)
        s += __shfl_xor_sync(0xFFFFFFFFu, s, o);
    if (lane == 0) wsum[warp] = s;
    __syncthreads();
    float bs = 0.0f;
#pragma unroll
    for (int w = 0; w < 8; w++) bs += wsum[w];

    const float inv = 1.0f / bs;
    e[tid]       = e0 * inv;
    e[tid + 256] = e1 * inv;
}

// ---------------------------------------------------------------------------
// 4) out[b,c,t] = sum_d attn[b,c,d]*V[b,d,t]    grid (T/128, C/128, B)
// ---------------------------------------------------------------------------
__global__ __launch_bounds__(256) void out_kernel(float* __restrict__ out)
{
    const int b  = blockIdx.z;
    const int m0 = blockIdx.y * 128;
    const int n0 = blockIdx.x * 128;
    const size_t base  = (size_t)b * CDIM * TDIM;
    const size_t ebase = (size_t)b * CDIM * CDIM;

    float acc[2][8][4];
    gemm_mma_tile<false>(g_e + ebase + (size_t)m0 * CDIM, CDIM,
                         g_v + base + n0, TDIM, CDIM, acc);

    const int lane = threadIdx.x & 31;
    const int wid  = threadIdx.x >> 5;
    const int wm = wid & 3, wn = wid >> 2;
#pragma unroll
    for (int mi = 0; mi < 2; mi++) {
#pragma unroll
        for (int ni = 0; ni < 8; ni++) {
            int r = m0 + wm * 32 + mi * 16 + (lane >> 2);
            int c = n0 + wn * 64 + ni * 8 + (lane & 3) * 2;
#pragma unroll
            for (int half = 0; half < 2; half++) {
                size_t off = base + (size_t)(r + half * 8) * TDIM + c;
                out[off]     = acc[mi][ni][half * 2 + 0];
                out[off + 1] = acc[mi][ni][half * 2 + 1];
            }
        }
    }
}

// ---------------------------------------------------------------------------
extern "C" void kernel_launch(void* const* d_in, const int* in_sizes, int n_in,
                              void* d_out, int out_size)
{
    const float* x  = (const float*)d_in[0];
    const float* gq = (const float*)d_in[1];
    const float* gk = (const float*)d_in[2];
    const float* gv = (const float*)d_in[3];
    const float* Wq = (const float*)d_in[4];
    const float* bq = (const float*)d_in[5];
    const float* Wk = (const float*)d_in[6];
    const float* bk = (const float*)d_in[7];
    const float* Wv = (const float*)d_in[8];
    const float* bv = (const float*)d_in[9];
    float* out = (float*)d_out;

    dim3 blk(256);

    dim3 g1(TDIM / 128, CDIM / 128, 3 * BSZ);
    qkv_kernel<<<g1, blk>>>(x, gq, gk, gv, Wq, bq, Wk, bk, Wv, bv);

    dim3 g2(CDIM / 128, CDIM / 128, BSZ);
    energy_kernel<<<g2, blk>>>();

    softmax_kernel<<<BSZ * CDIM, blk>>>();

    dim3 g4(TDIM / 128, CDIM / 128, BSZ);
    out_kernel<<<g4, blk>>>(out);
}

// round 5
// speedup vs baseline: 3.8651x; 1.6868x over previous
#include <cuda_runtime.h>
#include <cuda_fp16.h>
#include <cstdint>

#define BSZ 32
#define CDIM 512
#define TDIM 1024
#define SCALE_F 0.04419417382415922f  // 1/sqrt(512)
#define CT (CDIM * TDIM)
#define CC (CDIM * CDIM)

// ---------------------------------------------------------------------------
// Scratch (allocation-free rule: __device__ globals)
// ---------------------------------------------------------------------------
__device__ __align__(16) __half g_wq[CC];                    // fp16(Wq) [d][c]
__device__ __align__(16) __half g_wk[CC];
__device__ __align__(16) __half g_wvh[CC], g_wvl[CC];        // split Wv
__device__ __align__(16) __half g_xh[(size_t)BSZ * CT];      // split x [b][c][t]
__device__ __align__(16) __half g_xl[(size_t)BSZ * CT];
__device__ __align__(16) __half g_q[(size_t)BSZ * CT];       // fp16 q [b][c][t]
__device__ __align__(16) __half g_k[(size_t)BSZ * CT];       // fp16 k [b][d][t]
__device__ __align__(16) __half g_vh[(size_t)BSZ * CT];      // split v [b][d][t]
__device__ __align__(16) __half g_vl[(size_t)BSZ * CT];
__device__ __align__(16) __half g_ah[(size_t)BSZ * CC];      // split attn [b][c][d]
__device__ __align__(16) __half g_al[(size_t)BSZ * CC];
__device__ __align__(16) float  g_e[(size_t)BSZ * CC];       // energy fp32 [b][c][d]

// SMEM strides (fp16 elems): A-type rows 80B apart, B-NN rows 272B apart
// (both give 8 distinct 16B chunks mod 128B -> conflict-free ldmatrix).
#define ASTR 40
#define BSTR 136

// ---------------------------------------------------------------------------
// PTX wrappers
// ---------------------------------------------------------------------------
__device__ __forceinline__ void ldsm4(uint32_t& r0, uint32_t& r1, uint32_t& r2, uint32_t& r3,
                                      const void* p) {
    uint32_t a = (uint32_t)__cvta_generic_to_shared(p);
    asm volatile("ldmatrix.sync.aligned.m8n8.x4.shared.b16 {%0,%1,%2,%3},[%4];"
                 : "=r"(r0), "=r"(r1), "=r"(r2), "=r"(r3) : "r"(a));
}
__device__ __forceinline__ void ldsm4t(uint32_t& r0, uint32_t& r1, uint32_t& r2, uint32_t& r3,
                                       const void* p) {
    uint32_t a = (uint32_t)__cvta_generic_to_shared(p);
    asm volatile("ldmatrix.sync.aligned.m8n8.x4.trans.shared.b16 {%0,%1,%2,%3},[%4];"
                 : "=r"(r0), "=r"(r1), "=r"(r2), "=r"(r3) : "r"(a));
}
__device__ __forceinline__ void mma_f16(float* d, const uint32_t* a, const uint32_t* b) {
    asm volatile(
        "mma.sync.aligned.m16n8k16.row.col.f32.f16.f16.f32 "
        "{%0,%1,%2,%3},{%4,%5,%6,%7},{%8,%9},{%0,%1,%2,%3};"
        : "+f"(d[0]), "+f"(d[1]), "+f"(d[2]), "+f"(d[3])
        : "r"(a[0]), "r"(a[1]), "r"(a[2]), "r"(a[3]), "r"(b[0]), "r"(b[1]));
}
__device__ __forceinline__ void cpa16(uint32_t dst, const void* src) {
    asm volatile("cp.async.cg.shared.global [%0], [%1], 16;" :: "r"(dst), "l"(src));
}
__device__ __forceinline__ void cpcommit() { asm volatile("cp.async.commit_group;"); }
__device__ __forceinline__ void cpwait1()  { asm volatile("cp.async.wait_group 1;"); }

__device__ __forceinline__ void split1(float f, __half& h, __half& l) {
    h = __float2half(f);
    l = __float2half(f - __half2float(h));
}

// ---------------------------------------------------------------------------
// Core: 128x128 block tile, BK=32, 256 threads (8 warps as 4m x 2n, warp 32x64).
// A [M,K] k-contig. BNT=false: B [K,N] n-contig (trans ldsm). BNT=true: B [N,K]
// k-contig (non-trans ldsm -> col frag). SPLIT: hi/lo planes, 3 MMAs (hh+hl+lh).
// 2-stage cp.async pipeline.
// ---------------------------------------------------------------------------
template <bool SPLIT, bool BNT>
__device__ __forceinline__ void mm_core(
    const __half* __restrict__ Ah, const __half* __restrict__ Al, int lda,
    const __half* __restrict__ Bh, const __half* __restrict__ Bl, int ldb,
    int K, char* sm, float acc[2][8][4])
{
    constexpr int AP = 128 * ASTR * 2;                   // 10240
    constexpr int BP = BNT ? 128 * ASTR * 2 : 32 * BSTR * 2;
    constexpr int NA = SPLIT ? 2 : 1;
    constexpr int OB_AL = AP;
    constexpr int OB_BH = NA * AP;
    constexpr int OB_BL = NA * AP + BP;
    constexpr int SB = NA * (AP + BP);

    const int tid  = threadIdx.x;
    const int lane = tid & 31;
    const int wid  = tid >> 5;
    const int wm   = wid & 3;
    const int wn   = wid >> 2;
    const uint32_t s0 = (uint32_t)__cvta_generic_to_shared(sm);

#pragma unroll
    for (int mi = 0; mi < 2; mi++)
#pragma unroll
        for (int ni = 0; ni < 8; ni++)
#pragma unroll
            for (int r = 0; r < 4; r++) acc[mi][ni][r] = 0.0f;

    auto stage = [&](int buf, int kt) {
        uint32_t sb = s0 + buf * SB;
        {   // A planes: 128 rows x 32 k
            int row = tid >> 1;
            int e0  = (tid & 1) * 16;
            uint32_t d = sb + (row * ASTR + e0) * 2;
            const __half* s = Ah + (size_t)row * lda + kt + e0;
            cpa16(d, s); cpa16(d + 16, s + 8);
            if (SPLIT) {
                const __half* s2 = Al + (size_t)row * lda + kt + e0;
                cpa16(d + OB_AL, s2); cpa16(d + OB_AL + 16, s2 + 8);
            }
        }
        if (BNT) {  // B planes: 128 n-rows x 32 k
            int row = tid >> 1;
            int e0  = (tid & 1) * 16;
            uint32_t d = sb + OB_BH + (row * ASTR + e0) * 2;
            const __half* s = Bh + (size_t)row * ldb + kt + e0;
            cpa16(d, s); cpa16(d + 16, s + 8);
            if (SPLIT) {
                const __half* s2 = Bl + (size_t)row * ldb + kt + e0;
                cpa16(d + BP, s2); cpa16(d + BP + 16, s2 + 8);
            }
        } else {    // B planes: 32 k-rows x 128 n
            int row = tid >> 3;
            int e0  = (tid & 7) * 16;
            uint32_t d = sb + OB_BH + (row * BSTR + e0) * 2;
            const __half* s = Bh + (size_t)(kt + row) * ldb + e0;
            cpa16(d, s); cpa16(d + 16, s + 8);
            if (SPLIT) {
                const __half* s2 = Bl + (size_t)(kt + row) * ldb + e0;
                cpa16(d + BP, s2); cpa16(d + BP + 16, s2 + 8);
            }
        }
    };

    stage(0, 0);
    cpcommit();
    const int NT = K / 32;
    for (int it = 0; it < NT; ++it) {
        if (it + 1 < NT) stage((it + 1) & 1, (it + 1) * 32);
        cpcommit();
        cpwait1();
        __syncthreads();
        char* buf = sm + (it & 1) * SB;
        const __half* sA_h = (const __half*)(buf);
        const __half* sA_l = (const __half*)(buf + OB_AL);
        const __half* sB_h = (const __half*)(buf + OB_BH);
        const __half* sB_l = (const __half*)(buf + OB_BL);

#pragma unroll
        for (int ks = 0; ks < 2; ++ks) {
            uint32_t ah[2][4], al[2][4];
#pragma unroll
            for (int mi = 0; mi < 2; mi++) {
                int arow = wm * 32 + mi * 16 + (lane & 15);
                int acol = ks * 16 + (lane >> 4) * 8;
                ldsm4(ah[mi][0], ah[mi][1], ah[mi][2], ah[mi][3], &sA_h[arow * ASTR + acol]);
                if (SPLIT)
                    ldsm4(al[mi][0], al[mi][1], al[mi][2], al[mi][3], &sA_l[arow * ASTR + acol]);
            }
            uint32_t bh[4][4], bl[4][4];
#pragma unroll
            for (int p = 0; p < 4; p++) {
                if (!BNT) {
                    int brow = ks * 16 + (lane & 15);
                    int bcol = wn * 64 + p * 16 + (lane >> 4) * 8;
                    ldsm4t(bh[p][0], bh[p][1], bh[p][2], bh[p][3], &sB_h[brow * BSTR + bcol]);
                    if (SPLIT)
                        ldsm4t(bl[p][0], bl[p][1], bl[p][2], bl[p][3], &sB_l[brow * BSTR + bcol]);
                } else {
                    int q    = lane >> 3;
                    int nrow = wn * 64 + p * 16 + (lane & 7) + ((q & 2) ? 8 : 0);
                    int kcol = ks * 16 + ((q & 1) ? 8 : 0);
                    ldsm4(bh[p][0], bh[p][1], bh[p][2], bh[p][3], &sB_h[nrow * ASTR + kcol]);
                    if (SPLIT)
                        ldsm4(bl[p][0], bl[p][1], bl[p][2], bl[p][3], &sB_l[nrow * ASTR + kcol]);
                }
            }
#pragma unroll
            for (int mi = 0; mi < 2; mi++)
#pragma unroll
                for (int p = 0; p < 4; p++)
#pragma unroll
                    for (int t = 0; t < 2; t++) {
                        const int ni = p * 2 + t;
                        mma_f16(acc[mi][ni], ah[mi], &bh[p][t * 2]);
                        if (SPLIT) {
                            mma_f16(acc[mi][ni], ah[mi], &bl[p][t * 2]);
                            mma_f16(acc[mi][ni], al[mi], &bh[p][t * 2]);
                        }
                    }
        }
        __syncthreads();
    }
}

// SMEM totals
#define SMEM_QK  (2 * (1 * (128 * ASTR * 2 + 32 * BSTR * 2)))   // 37888
#define SMEM_SPL (2 * (2 * (128 * ASTR * 2 + 32 * BSTR * 2)))   // 75776
#define SMEM_EN  (2 * (1 * (128 * ASTR * 2 + 128 * ASTR * 2)))  // 40960

// ---------------------------------------------------------------------------
// Prep kernels
// ---------------------------------------------------------------------------
union H4 { __half h[4]; uint2 u; };

__global__ __launch_bounds__(256) void wprep(
    const float* __restrict__ Wq, const float* __restrict__ Wk, const float* __restrict__ Wv)
{
    const int m = blockIdx.y;
    size_t i = ((size_t)blockIdx.x * 256 + threadIdx.x) * 4;
    const float* W = (m == 0) ? Wq : ((m == 1) ? Wk : Wv);
    float4 v = *reinterpret_cast<const float4*>(W + i);
    float f[4] = {v.x, v.y, v.z, v.w};
    H4 h, l;
#pragma unroll
    for (int k = 0; k < 4; k++) split1(f[k], h.h[k], l.h[k]);
    if (m == 0)      *reinterpret_cast<uint2*>(&g_wq[i]) = h.u;
    else if (m == 1) *reinterpret_cast<uint2*>(&g_wk[i]) = h.u;
    else { *reinterpret_cast<uint2*>(&g_wvh[i]) = h.u;
           *reinterpret_cast<uint2*>(&g_wvl[i]) = l.u; }
}

__global__ __launch_bounds__(256) void xprep(const float* __restrict__ x)
{
    size_t i = ((size_t)blockIdx.x * 256 + threadIdx.x) * 4;
    float4 v = *reinterpret_cast<const float4*>(x + i);
    float f[4] = {v.x, v.y, v.z, v.w};
    H4 h, l;
#pragma unroll
    for (int k = 0; k < 4; k++) split1(f[k], h.h[k], l.h[k]);
    *reinterpret_cast<uint2*>(&g_xh[i]) = h.u;
    *reinterpret_cast<uint2*>(&g_xl[i]) = l.u;
}

// ---------------------------------------------------------------------------
// 1a) q/k projection: fp16 single-pass.  grid (8, 4, 64), z = m*32+b
// ---------------------------------------------------------------------------
__global__ __launch_bounds__(256) void qk_mm(
    const float* __restrict__ gq, const float* __restrict__ gk,
    const float* __restrict__ bq, const float* __restrict__ bk)
{
    extern __shared__ char dsm[];
    const int z = blockIdx.z;
    const int b = z & 31;
    const int m = z >> 5;
    const float* gate = m ? gk : gq;
    const float* bias = m ? bk : bq;
    __half* outp = m ? g_k : g_q;

    const int m0 = blockIdx.y * 128;  // d
    const int n0 = blockIdx.x * 128;  // t
    const size_t base = (size_t)b * CT;
    const __half* A = (m ? g_wk : g_wq) + (size_t)m0 * CDIM;
    const __half* B = g_xh + base + n0;

    float acc[2][8][4];
    mm_core<false, false>(A, nullptr, CDIM, B, nullptr, TDIM, CDIM, dsm, acc);

    const int lane = threadIdx.x & 31;
    const int wid  = threadIdx.x >> 5;
    const int wm = wid & 3, wn = wid >> 2;
#pragma unroll
    for (int mi = 0; mi < 2; mi++)
#pragma unroll
        for (int ni = 0; ni < 8; ni++) {
            int r = m0 + wm * 32 + mi * 16 + (lane >> 2);
            int c = n0 + wn * 64 + ni * 8 + (lane & 3) * 2;
#pragma unroll
            for (int h = 0; h < 2; h++) {
                int d = r + h * 8;
                float bi = bias[d];
                size_t off = base + (size_t)d * TDIM + c;
                float2 g = *reinterpret_cast<const float2*>(gate + off);
                __half2 o = __floats2half2_rn((acc[mi][ni][h * 2 + 0] + bi) * g.x,
                                              (acc[mi][ni][h * 2 + 1] + bi) * g.y);
                *reinterpret_cast<__half2*>(outp + off) = o;
            }
        }
}

// ---------------------------------------------------------------------------
// 1b) v projection: split-3.  grid (8, 4, 32)
// ---------------------------------------------------------------------------
__global__ __launch_bounds__(256) void v_mm(
    const float* __restrict__ gv, const float* __restrict__ bv)
{
    extern __shared__ char dsm[];
    const int b  = blockIdx.z;
    const int m0 = blockIdx.y * 128;  // d
    const int n0 = blockIdx.x * 128;  // t
    const size_t base = (size_t)b * CT;

    float acc[2][8][4];
    mm_core<true, false>(g_wvh + (size_t)m0 * CDIM, g_wvl + (size_t)m0 * CDIM, CDIM,
                         g_xh + base + n0, g_xl + base + n0, TDIM, CDIM, dsm, acc);

    const int lane = threadIdx.x & 31;
    const int wid  = threadIdx.x >> 5;
    const int wm = wid & 3, wn = wid >> 2;
#pragma unroll
    for (int mi = 0; mi < 2; mi++)
#pragma unroll
        for (int ni = 0; ni < 8; ni++) {
            int r = m0 + wm * 32 + mi * 16 + (lane >> 2);
            int c = n0 + wn * 64 + ni * 8 + (lane & 3) * 2;
#pragma unroll
            for (int h = 0; h < 2; h++) {
                int d = r + h * 8;
                float bi = bv[d];
                size_t off = base + (size_t)d * TDIM + c;
                float2 g = *reinterpret_cast<const float2*>(gv + off);
                float v0 = (acc[mi][ni][h * 2 + 0] + bi) * g.x;
                float v1 = (acc[mi][ni][h * 2 + 1] + bi) * g.y;
                __half h0, l0, h1, l1;
                split1(v0, h0, l0);
                split1(v1, h1, l1);
                *reinterpret_cast<__half2*>(g_vh + off) = __halves2half2(h0, h1);
                *reinterpret_cast<__half2*>(g_vl + off) = __halves2half2(l0, l1);
            }
        }
}

// ---------------------------------------------------------------------------
// 2) energy: fp16 single-pass NT.  grid (4, 4, 32)
// ---------------------------------------------------------------------------
__global__ __launch_bounds__(256) void energy_mm()
{
    extern __shared__ char dsm[];
    const int b  = blockIdx.z;
    const int m0 = blockIdx.y * 128;  // c
    const int n0 = blockIdx.x * 128;  // d
    const size_t base = (size_t)b * CT;

    float acc[2][8][4];
    mm_core<false, true>(g_q + base + (size_t)m0 * TDIM, nullptr, TDIM,
                         g_k + base + (size_t)n0 * TDIM, nullptr, TDIM, TDIM, dsm, acc);

    const int lane = threadIdx.x & 31;
    const int wid  = threadIdx.x >> 5;
    const int wm = wid & 3, wn = wid >> 2;
    const size_t ebase = (size_t)b * CC;
#pragma unroll
    for (int mi = 0; mi < 2; mi++)
#pragma unroll
        for (int ni = 0; ni < 8; ni++) {
            int r = m0 + wm * 32 + mi * 16 + (lane >> 2);
            int c = n0 + wn * 64 + ni * 8 + (lane & 3) * 2;
#pragma unroll
            for (int h = 0; h < 2; h++) {
                size_t off = ebase + (size_t)(r + h * 8) * CDIM + c;
                *reinterpret_cast<float2*>(g_e + off) =
                    make_float2(acc[mi][ni][h * 2 + 0] * SCALE_F,
                                acc[mi][ni][h * 2 + 1] * SCALE_F);
            }
        }
}

// ---------------------------------------------------------------------------
// 3) softmax over d (512) -> split fp16 attn planes.  grid 16384 x 256
// ---------------------------------------------------------------------------
__global__ __launch_bounds__(256) void softmax_kernel()
{
    const size_t row = blockIdx.x;
    const float* e = g_e + row * CDIM;
    const int tid  = threadIdx.x;
    const int lane = tid & 31;
    const int warp = tid >> 5;

    __shared__ float wmax[8], wsum[8];

    float v0 = e[tid];
    float v1 = e[tid + 256];
    float m = fmaxf(v0, v1);
#pragma unroll
    for (int o = 16; o > 0; o >>= 1) m = fmaxf(m, __shfl_xor_sync(0xFFFFFFFFu, m, o));
    if (lane == 0) wmax[warp] = m;
    __syncthreads();
    float bm = wmax[0];
#pragma unroll
    for (int w = 1; w < 8; w++) bm = fmaxf(bm, wmax[w]);

    float e0 = __expf(v0 - bm);
    float e1 = __expf(v1 - bm);
    float s = e0 + e1;
#pragma unroll
    for (int o = 16; o > 0; o >>= 1) s += __shfl_xor_sync(0xFFFFFFFFu, s, o);
    if (lane == 0) wsum[warp] = s;
    __syncthreads();
    float bs = 0.0f;
#pragma unroll
    for (int w = 0; w < 8; w++) bs += wsum[w];

    const float inv = 1.0f / bs;
    float p0 = e0 * inv, p1 = e1 * inv;
    __half h0, l0, h1, l1;
    split1(p0, h0, l0);
    split1(p1, h1, l1);
    g_ah[row * CDIM + tid]       = h0;
    g_al[row * CDIM + tid]       = l0;
    g_ah[row * CDIM + tid + 256] = h1;
    g_al[row * CDIM + tid + 256] = l1;
}

// ---------------------------------------------------------------------------
// 4) out = attn @ v : split-3 NN.  grid (8, 4, 32)
// ---------------------------------------------------------------------------
__global__ __launch_bounds__(256) void out_mm(float* __restrict__ out)
{
    extern __shared__ char dsm[];
    const int b  = blockIdx.z;
    const int m0 = blockIdx.y * 128;  // c
    const int n0 = blockIdx.x * 128;  // t
    const size_t base  = (size_t)b * CT;
    const size_t ebase = (size_t)b * CC;

    float acc[2][8][4];
    mm_core<true, false>(g_ah + ebase + (size_t)m0 * CDIM, g_al + ebase + (size_t)m0 * CDIM, CDIM,
                         g_vh + base + n0, g_vl + base + n0, TDIM, CDIM, dsm, acc);

    const int lane = threadIdx.x & 31;
    const int wid  = threadIdx.x >> 5;
    const int wm = wid & 3, wn = wid >> 2;
#pragma unroll
    for (int mi = 0; mi < 2; mi++)
#pragma unroll
        for (int ni = 0; ni < 8; ni++) {
            int r = m0 + wm * 32 + mi * 16 + (lane >> 2);
            int c = n0 + wn * 64 + ni * 8 + (lane & 3) * 2;
#pragma unroll
            for (int h = 0; h < 2; h++) {
                size_t off = base + (size_t)(r + h * 8) * TDIM + c;
                *reinterpret_cast<float2*>(out + off) =
                    make_float2(acc[mi][ni][h * 2 + 0], acc[mi][ni][h * 2 + 1]);
            }
        }
}

// ---------------------------------------------------------------------------
extern "C" void kernel_launch(void* const* d_in, const int* in_sizes, int n_in,
                              void* d_out, int out_size)
{
    const float* x  = (const float*)d_in[0];
    const float* gq = (const float*)d_in[1];
    const float* gk = (const float*)d_in[2];
    const float* gv = (const float*)d_in[3];
    const float* Wq = (const float*)d_in[4];
    const float* bq = (const float*)d_in[5];
    const float* Wk = (const float*)d_in[6];
    const float* bk = (const float*)d_in[7];
    const float* Wv = (const float*)d_in[8];
    const float* bv = (const float*)d_in[9];
    float* out = (float*)d_out;

    cudaFuncSetAttribute(qk_mm,     cudaFuncAttributeMaxDynamicSharedMemorySize, SMEM_QK);
    cudaFuncSetAttribute(v_mm,      cudaFuncAttributeMaxDynamicSharedMemorySize, SMEM_SPL);
    cudaFuncSetAttribute(energy_mm, cudaFuncAttributeMaxDynamicSharedMemorySize, SMEM_EN);
    cudaFuncSetAttribute(out_mm,    cudaFuncAttributeMaxDynamicSharedMemorySize, SMEM_SPL);

    wprep<<<dim3(CC / 1024, 3), 256>>>(Wq, Wk, Wv);
    xprep<<<(unsigned)(((size_t)BSZ * CT) / 1024), 256>>>(x);

    qk_mm<<<dim3(TDIM / 128, CDIM / 128, 2 * BSZ), 256, SMEM_QK>>>(gq, gk, bq, bk);
    v_mm<<<dim3(TDIM / 128, CDIM / 128, BSZ), 256, SMEM_SPL>>>(gv, bv);

    energy_mm<<<dim3(CDIM / 128, CDIM / 128, BSZ), 256, SMEM_EN>>>();

    softmax_kernel<<<BSZ * CDIM, 256>>>();

    out_mm<<<dim3(TDIM / 128, CDIM / 128, BSZ), 256, SMEM_SPL>>>(out);
}

// round 8
// speedup vs baseline: 4.8054x; 1.2433x over previous
#include <cuda_runtime.h>
#include <cuda_fp16.h>
#include <cstdint>

#define BSZ 32
#define CDIM 512
#define TDIM 1024
#define SCALE_F 0.04419417382415922f  // 1/sqrt(512)
#define CT (CDIM * TDIM)
#define CC (CDIM * CDIM)

// ---------------------------------------------------------------------------
// Scratch (allocation-free rule: __device__ globals)
// ---------------------------------------------------------------------------
__device__ __align__(16) __half g_w[3 * CC];                 // fp16 W [m][d][c]
__device__ __align__(16) __half g_x[(size_t)BSZ * CT];       // fp16 x [b][c][t]
__device__ __align__(16) __half g_q[(size_t)BSZ * CT];       // fp16 q [b][c][t]
__device__ __align__(16) __half g_k[(size_t)BSZ * CT];       // fp16 k [b][d][t]
__device__ __align__(16) __half g_v[(size_t)BSZ * CT];       // fp16 v [b][d][t]
__device__ __align__(16) __half g_a[(size_t)BSZ * CC];       // fp16 attn [b][c][d]
__device__ __align__(16) float  g_e[(size_t)BSZ * CC];       // energy fp32 [b][c][d]

// SMEM strides (fp16 elems): A rows 144B apart (16B shift/row mod 128B),
// B-NN rows 272B apart -> both conflict-free for ldmatrix.
#define ASTR 72
#define BSTR 136

// ---------------------------------------------------------------------------
// PTX wrappers
// ---------------------------------------------------------------------------
__device__ __forceinline__ void ldsm4(uint32_t& r0, uint32_t& r1, uint32_t& r2, uint32_t& r3,
                                      const void* p) {
    uint32_t a = (uint32_t)__cvta_generic_to_shared(p);
    asm volatile("ldmatrix.sync.aligned.m8n8.x4.shared.b16 {%0,%1,%2,%3},[%4];"
                 : "=r"(r0), "=r"(r1), "=r"(r2), "=r"(r3) : "r"(a));
}
__device__ __forceinline__ void ldsm4t(uint32_t& r0, uint32_t& r1, uint32_t& r2, uint32_t& r3,
                                       const void* p) {
    uint32_t a = (uint32_t)__cvta_generic_to_shared(p);
    asm volatile("ldmatrix.sync.aligned.m8n8.x4.trans.shared.b16 {%0,%1,%2,%3},[%4];"
                 : "=r"(r0), "=r"(r1), "=r"(r2), "=r"(r3) : "r"(a));
}
__device__ __forceinline__ void mma_f16(float* d, const uint32_t* a, const uint32_t* b) {
    asm volatile(
        "mma.sync.aligned.m16n8k16.row.col.f32.f16.f16.f32 "
        "{%0,%1,%2,%3},{%4,%5,%6,%7},{%8,%9},{%0,%1,%2,%3};"
        : "+f"(d[0]), "+f"(d[1]), "+f"(d[2]), "+f"(d[3])
        : "r"(a[0]), "r"(a[1]), "r"(a[2]), "r"(a[3]), "r"(b[0]), "r"(b[1]));
}
__device__ __forceinline__ void cpa16(uint32_t dst, const void* src) {
    asm volatile("cp.async.cg.shared.global [%0], [%1], 16;" :: "r"(dst), "l"(src));
}
__device__ __forceinline__ void cpcommit() { asm volatile("cp.async.commit_group;"); }
__device__ __forceinline__ void cpwait1()  { asm volatile("cp.async.wait_group 1;"); }

// ---------------------------------------------------------------------------
// Core: 128x128 block tile, BK=64, 256 threads (8 warps 4m x 2n, warp 32x64),
// fp16 single-pass, 2-stage cp.async double buffer.
// A [M,K] k-contig. BNT=false: B [K,N] n-contig. BNT=true: B [N,K] k-contig.
// ---------------------------------------------------------------------------
template <bool BNT>
__device__ __forceinline__ void mm_core(
    const __half* __restrict__ A, int lda,
    const __half* __restrict__ B, int ldb,
    int K, char* sm, float acc[2][8][4])
{
    constexpr int AP = 128 * ASTR * 2;                     // 18432
    constexpr int BP = BNT ? 128 * ASTR * 2 : 64 * BSTR * 2;
    constexpr int SB = AP + BP;

    const int tid  = threadIdx.x;
    const int lane = tid & 31;
    const int wid  = tid >> 5;
    const int wm   = wid & 3;
    const int wn   = wid >> 2;
    const uint32_t s0 = (uint32_t)__cvta_generic_to_shared(sm);

#pragma unroll
    for (int mi = 0; mi < 2; mi++)
#pragma unroll
        for (int ni = 0; ni < 8; ni++)
#pragma unroll
            for (int r = 0; r < 4; r++) acc[mi][ni][r] = 0.0f;

    auto stage = [&](int buf, int kt) {
        uint32_t sb = s0 + buf * SB;
        {   // A: 128 rows x 64 k, 64B per thread
            int row = tid >> 1;
            int e0  = (tid & 1) * 32;
            uint32_t d = sb + (row * ASTR + e0) * 2;
            const __half* s = A + (size_t)row * lda + kt + e0;
#pragma unroll
            for (int j = 0; j < 4; j++) cpa16(d + j * 16, s + j * 8);
        }
        if (BNT) {  // B: 128 n-rows x 64 k
            int row = tid >> 1;
            int e0  = (tid & 1) * 32;
            uint32_t d = sb + AP + (row * ASTR + e0) * 2;
            const __half* s = B + (size_t)row * ldb + kt + e0;
#pragma unroll
            for (int j = 0; j < 4; j++) cpa16(d + j * 16, s + j * 8);
        } else {    // B: 64 k-rows x 128 n
            int row = tid >> 2;
            int e0  = (tid & 3) * 32;
            uint32_t d = sb + AP + (row * BSTR + e0) * 2;
            const __half* s = B + (size_t)(kt + row) * ldb + e0;
#pragma unroll
            for (int j = 0; j < 4; j++) cpa16(d + j * 16, s + j * 8);
        }
    };

    stage(0, 0);
    cpcommit();
    const int NT = K / 64;
    for (int it = 0; it < NT; ++it) {
        if (it + 1 < NT) stage((it + 1) & 1, (it + 1) * 64);
        cpcommit();
        cpwait1();
        __syncthreads();
        char* buf = sm + (it & 1) * SB;
        const __half* sA = (const __half*)buf;
        const __half* sB = (const __half*)(buf + AP);

#pragma unroll
        for (int ks = 0; ks < 4; ++ks) {
            uint32_t ah[2][4];
#pragma unroll
            for (int mi = 0; mi < 2; mi++) {
                int arow = wm * 32 + mi * 16 + (lane & 15);
                int acol = ks * 16 + (lane >> 4) * 8;
                ldsm4(ah[mi][0], ah[mi][1], ah[mi][2], ah[mi][3], &sA[arow * ASTR + acol]);
            }
            uint32_t bh[4][4];
#pragma unroll
            for (int p = 0; p < 4; p++) {
                if (!BNT) {
                    int brow = ks * 16 + (lane & 15);
                    int bcol = wn * 64 + p * 16 + (lane >> 4) * 8;
                    ldsm4t(bh[p][0], bh[p][1], bh[p][2], bh[p][3], &sB[brow * BSTR + bcol]);
                } else {
                    int q    = lane >> 3;
                    int nrow = wn * 64 + p * 16 + (lane & 7) + ((q & 2) ? 8 : 0);
                    int kcol = ks * 16 + ((q & 1) ? 8 : 0);
                    ldsm4(bh[p][0], bh[p][1], bh[p][2], bh[p][3], &sB[nrow * ASTR + kcol]);
                }
            }
#pragma unroll
            for (int mi = 0; mi < 2; mi++)
#pragma unroll
                for (int p = 0; p < 4; p++)
#pragma unroll
                    for (int t = 0; t < 2; t++)
                        mma_f16(acc[mi][p * 2 + t], ah[mi], &bh[p][t * 2]);
        }
        __syncthreads();
    }
}

#define SMEM_NN (2 * (128 * ASTR * 2 + 64 * BSTR * 2))    // 71680
#define SMEM_NT (2 * (128 * ASTR * 2 + 128 * ASTR * 2))   // 73728

// ---------------------------------------------------------------------------
// Prep kernels: fp16 casts
// ---------------------------------------------------------------------------
__global__ __launch_bounds__(256) void wprep(
    const float* __restrict__ Wq, const float* __restrict__ Wk, const float* __restrict__ Wv)
{
    const int m = blockIdx.y;
    const float* W = (m == 0) ? Wq : ((m == 1) ? Wk : Wv);
    size_t i = ((size_t)blockIdx.x * 256 + threadIdx.x) * 8;
    float4 a = *reinterpret_cast<const float4*>(W + i);
    float4 b = *reinterpret_cast<const float4*>(W + i + 4);
    union { __half h[8]; uint4 u; } o;
    o.h[0] = __float2half(a.x); o.h[1] = __float2half(a.y);
    o.h[2] = __float2half(a.z); o.h[3] = __float2half(a.w);
    o.h[4] = __float2half(b.x); o.h[5] = __float2half(b.y);
    o.h[6] = __float2half(b.z); o.h[7] = __float2half(b.w);
    *reinterpret_cast<uint4*>(&g_w[(size_t)m * CC + i]) = o.u;
}

__global__ __launch_bounds__(256) void xprep(const float* __restrict__ x)
{
    size_t i = ((size_t)blockIdx.x * 256 + threadIdx.x) * 8;
    float4 a = *reinterpret_cast<const float4*>(x + i);
    float4 b = *reinterpret_cast<const float4*>(x + i + 4);
    union { __half h[8]; uint4 u; } o;
    o.h[0] = __float2half(a.x); o.h[1] = __float2half(a.y);
    o.h[2] = __float2half(a.z); o.h[3] = __float2half(a.w);
    o.h[4] = __float2half(b.x); o.h[5] = __float2half(b.y);
    o.h[6] = __float2half(b.z); o.h[7] = __float2half(b.w);
    *reinterpret_cast<uint4*>(&g_x[i]) = o.u;
}

// ---------------------------------------------------------------------------
// 1) q/k/v projection: out[ch,t] = fp16(gate * (W @ x + bias))
//    grid (8, 4, 96), z = m*32 + b
// ---------------------------------------------------------------------------
__global__ __launch_bounds__(256) void qkv_mm(
    const float* __restrict__ gq, const float* __restrict__ gk, const float* __restrict__ gv,
    const float* __restrict__ bq, const float* __restrict__ bk, const float* __restrict__ bv)
{
    extern __shared__ char dsm[];
    const int z = blockIdx.z;
    const int b = z & 31;
    const int m = z >> 5;
    const float* gate = (m == 0) ? gq : ((m == 1) ? gk : gv);
    const float* bias = (m == 0) ? bq : ((m == 1) ? bk : bv);
    __half* outp      = (m == 0) ? g_q : ((m == 1) ? g_k : g_v);

    const int m0 = blockIdx.y * 128;  // d
    const int n0 = blockIdx.x * 128;  // t
    const size_t base = (size_t)b * CT;

    float acc[2][8][4];
    mm_core<false>(g_w + (size_t)m * CC + (size_t)m0 * CDIM, CDIM,
                   g_x + base + n0, TDIM, CDIM, dsm, acc);

    const int lane = threadIdx.x & 31;
    const int wid  = threadIdx.x >> 5;
    const int wm = wid & 3, wn = wid >> 2;
#pragma unroll
    for (int mi = 0; mi < 2; mi++)
#pragma unroll
        for (int ni = 0; ni < 8; ni++) {
            int r = m0 + wm * 32 + mi * 16 + (lane >> 2);
            int c = n0 + wn * 64 + ni * 8 + (lane & 3) * 2;
#pragma unroll
            for (int h = 0; h < 2; h++) {
                int d = r + h * 8;
                float bi = bias[d];
                size_t off = base + (size_t)d * TDIM + c;
                float2 g = *reinterpret_cast<const float2*>(gate + off);
                *reinterpret_cast<__half2*>(outp + off) =
                    __floats2half2_rn((acc[mi][ni][h * 2 + 0] + bi) * g.x,
                                      (acc[mi][ni][h * 2 + 1] + bi) * g.y);
            }
        }
}

// ---------------------------------------------------------------------------
// 2) energy: E[c,d] = SCALE * sum_t q[c,t] k[d,t]   grid (4, 4, 32)
// ---------------------------------------------------------------------------
__global__ __launch_bounds__(256) void energy_mm()
{
    extern __shared__ char dsm[];
    const int b  = blockIdx.z;
    const int m0 = blockIdx.y * 128;  // c
    const int n0 = blockIdx.x * 128;  // d
    const size_t base = (size_t)b * CT;

    float acc[2][8][4];
    mm_core<true>(g_q + base + (size_t)m0 * TDIM, TDIM,
                  g_k + base + (size_t)n0 * TDIM, TDIM, TDIM, dsm, acc);

    const int lane = threadIdx.x & 31;
    const int wid  = threadIdx.x >> 5;
    const int wm = wid & 3, wn = wid >> 2;
    const size_t ebase = (size_t)b * CC;
#pragma unroll
    for (int mi = 0; mi < 2; mi++)
#pragma unroll
        for (int ni = 0; ni < 8; ni++) {
            int r = m0 + wm * 32 + mi * 16 + (lane >> 2);
            int c = n0 + wn * 64 + ni * 8 + (lane & 3) * 2;
#pragma unroll
            for (int h = 0; h < 2; h++) {
                size_t off = ebase + (size_t)(r + h * 8) * CDIM + c;
                *reinterpret_cast<float2*>(g_e + off) =
                    make_float2(acc[mi][ni][h * 2 + 0] * SCALE_F,
                                acc[mi][ni][h * 2 + 1] * SCALE_F);
            }
        }
}

// ---------------------------------------------------------------------------
// 3) softmax over d (512) -> fp16 attn.  grid 16384 x 256
// ---------------------------------------------------------------------------
__global__ __launch_bounds__(256) void softmax_kernel()
{
    const size_t row = blockIdx.x;
    const float* e = g_e + row * CDIM;
    const int tid  = threadIdx.x;
    const int lane = tid & 31;
    const int warp = tid >> 5;

    __shared__ float wmax[8], wsum[8];

    float v0 = e[tid];
    float v1 = e[tid + 256];
    float m = fmaxf(v0, v1);
#pragma unroll
    for (int o = 16; o > 0; o >>= 1) m = fmaxf(m, __shfl_xor_sync(0xFFFFFFFFu, m, o));
    if (lane == 0) wmax[warp] = m;
    __syncthreads();
    float bm = wmax[0];
#pragma unroll
    for (int w = 1; w < 8; w++) bm = fmaxf(bm, wmax[w]);

    float e0 = __expf(v0 - bm);
    float e1 = __expf(v1 - bm);
    float s = e0 + e1;
#pragma unroll
    for (int o = 16; o > 0; o >>= 1) s += __shfl_xor_sync(0xFFFFFFFFu, s, o);
    if (lane == 0) wsum[warp] = s;
    __syncthreads();
    float bs = 0.0f;
#pragma unroll
    for (int w = 0; w < 8; w++) bs += wsum[w];

    const float inv = 1.0f / bs;
    g_a[row * CDIM + tid]       = __float2half(e0 * inv);
    g_a[row * CDIM + tid + 256] = __float2half(e1 * inv);
}

// ---------------------------------------------------------------------------
// 4) out[c,t] = sum_d attn[c,d] v[d,t]   grid (8, 4, 32)
// ---------------------------------------------------------------------------
__global__ __launch_bounds__(256) void out_mm(float* __restrict__ out)
{
    extern __shared__ char dsm[];
    const int b  = blockIdx.z;
    const int m0 = blockIdx.y * 128;  // c
    const int n0 = blockIdx.x * 128;  // t
    const size_t base  = (size_t)b * CT;
    const size_t ebase = (size_t)b * CC;

    float acc[2][8][4];
    mm_core<false>(g_a + ebase + (size_t)m0 * CDIM, CDIM,
                   g_v + base + n0, TDIM, CDIM, dsm, acc);

    const int lane = threadIdx.x & 31;
    const int wid  = threadIdx.x >> 5;
    const int wm = wid & 3, wn = wid >> 2;
#pragma unroll
    for (int mi = 0; mi < 2; mi++)
#pragma unroll
        for (int ni = 0; ni < 8; ni++) {
            int r = m0 + wm * 32 + mi * 16 + (lane >> 2);
            int c = n0 + wn * 64 + ni * 8 + (lane & 3) * 2;
#pragma unroll
            for (int h = 0; h < 2; h++) {
                size_t off = base + (size_t)(r + h * 8) * TDIM + c;
                *reinterpret_cast<float2*>(out + off) =
                    make_float2(acc[mi][ni][h * 2 + 0], acc[mi][ni][h * 2 + 1]);
            }
        }
}

// ---------------------------------------------------------------------------
extern "C" void kernel_launch(void* const* d_in, const int* in_sizes, int n_in,
                              void* d_out, int out_size)
{
    const float* x  = (const float*)d_in[0];
    const float* gq = (const float*)d_in[1];
    const float* gk = (const float*)d_in[2];
    const float* gv = (const float*)d_in[3];
    const float* Wq = (const float*)d_in[4];
    const float* bq = (const float*)d_in[5];
    const float* Wk = (const float*)d_in[6];
    const float* bk = (const float*)d_in[7];
    const float* Wv = (const float*)d_in[8];
    const float* bv = (const float*)d_in[9];
    float* out = (float*)d_out;

    cudaFuncSetAttribute(qkv_mm,    cudaFuncAttributeMaxDynamicSharedMemorySize, SMEM_NN);
    cudaFuncSetAttribute(energy_mm, cudaFuncAttributeMaxDynamicSharedMemorySize, SMEM_NT);
    cudaFuncSetAttribute(out_mm,    cudaFuncAttributeMaxDynamicSharedMemorySize, SMEM_NN);

    wprep<<<dim3(CC / 2048, 3), 256>>>(Wq, Wk, Wv);
    xprep<<<(unsigned)(((size_t)BSZ * CT) / 2048), 256>>>(x);

    qkv_mm<<<dim3(TDIM / 128, CDIM / 128, 3 * BSZ), 256, SMEM_NN>>>(gq, gk, gv, bq, bk, bv);

    energy_mm<<<dim3(CDIM / 128, CDIM / 128, BSZ), 256, SMEM_NT>>>();

    softmax_kernel<<<BSZ * CDIM, 256>>>();

    out_mm<<<dim3(TDIM / 128, CDIM / 128, BSZ), 256, SMEM_NN>>>(out);
}